// round 8
// baseline (speedup 1.0000x reference)
#include <cuda_runtime.h>
#include <math.h>

#define Nn 8192
#define Kk 64
#define Dd 512
#define FD 2048   // 4*D

typedef unsigned long long u64t;

// ---- packed f32x2 ops (Blackwell FFMA2; each half = independent IEEE rn FMA) ----
#define PACKF2(d, lo, hi)  asm("mov.b64 %0, {%1, %2};" : "=l"(d) : "f"(lo), "f"(hi))
#define UNPACKF2(lo, hi, s) asm("mov.b64 {%0, %1}, %2;" : "=f"(lo), "=f"(hi) : "l"(s))
#define FMA2(d, a, b, c)   asm("fma.rn.f32x2 %0, %1, %2, %3;" : "=l"(d) : "l"(a), "l"(b), "l"(c))

// Scratch (allocation-free device globals)
__device__ float g_P[(size_t)Nn * FD];      // 64 MB: partial chain f@W_L^T (no biases)
__device__ float g_hw[(size_t)Nn * FD];     // 64 MB: h@W_hh^T per step
__device__ float g_h[2][(size_t)Nn * Dd];   // ping/pong h
__device__ float g_c[(size_t)Nn * Dd];      // cell state
__device__ float g_r[(size_t)Nn * Dd];      // r = a @ G
__device__ float g_a[(size_t)Nn * Kk];      // softmax weights

// ---- XLA EmitFastTanh f32 (verbatim) ----
__device__ __forceinline__ float tanh_xla(float x) {
    float ax = fabsf(x);
    float xc = fminf(fmaxf(x, -7.90531110763549805f), 7.90531110763549805f);
    float x2 = __fmul_rn(xc, xc);
    float p = -2.76076847742355e-16f;
    p = __fadd_rn(__fmul_rn(p, x2), 2.00018790482477e-13f);
    p = __fadd_rn(__fmul_rn(p, x2), -8.60467152213735e-11f);
    p = __fadd_rn(__fmul_rn(p, x2), 5.12229709037114e-08f);
    p = __fadd_rn(__fmul_rn(p, x2), 1.48572235717979e-05f);
    p = __fadd_rn(__fmul_rn(p, x2), 6.37261928875436e-04f);
    p = __fadd_rn(__fmul_rn(p, x2), 4.89352455891786e-03f);
    float num = __fmul_rn(xc, p);
    float q = 1.19825839466702e-06f;
    q = __fadd_rn(__fmul_rn(q, x2), 1.18534705686654e-04f);
    q = __fadd_rn(__fmul_rn(q, x2), 2.26843463243900e-03f);
    q = __fadd_rn(__fmul_rn(q, x2), 4.89352518554385e-03f);
    float r = __fdiv_rn(num, q);
    return (ax < 0.0004f) ? x : r;
}
__device__ __forceinline__ float sig_xla(float x) {
    return __fadd_rn(0.5f, __fmul_rn(0.5f, tanh_xla(__fmul_rn(0.5f, x))));
}

// ---------------- init: h0 = f, c = 0 ----------------
__global__ void k_init(const float* __restrict__ f) {
    int i = blockIdx.x * 256 + threadIdx.x;
    g_h[0][i] = f[i];
    g_c[i] = 0.f;
}

// ---------------- generic SGEMM via FFMA2, zero-MOV operands ----------------
// 128x128 tile, 256 threads, 8x8/thread (4 col-pairs). A tile duplicated {v,v} in smem.
__global__ __launch_bounds__(256, 2) void k_gemm(const float* __restrict__ Aopt, int cur,
                                                 const float* __restrict__ B, long bstride,
                                                 float* __restrict__ C) {
    __shared__ float As2[2][16][256];   // duplicated: As2[k][2*row] = As2[k][2*row+1] = A
    __shared__ float Bs[2][16][128];
    const float* __restrict__ A = Aopt ? Aopt : g_h[cur];
    const int jb = blockIdx.x * 128, mb = blockIdx.y * 128;
    const int tid = threadIdx.x, tx = tid & 15, ty = tid >> 4;
    const int lrow = tid >> 1, lk = (tid & 1) << 3;
    u64t acc2[8][4];
#pragma unroll
    for (int i = 0; i < 8; i++)
#pragma unroll
        for (int q = 0; q < 4; q++) acc2[i][q] = 0ull;

    const float* Arow = A + (size_t)(mb + lrow) * Dd + lk;
    const float* Brow = B + (size_t)(jb + lrow) * bstride + lk;

    float4 a0 = *(const float4*)(Arow), a1 = *(const float4*)(Arow + 4);
    float4 b0 = *(const float4*)(Brow), b1 = *(const float4*)(Brow + 4);
#pragma unroll
    for (int j = 0; j < 4; j++) {
        float av = (&a0.x)[j], aw = (&a1.x)[j];
        *(float2*)&As2[0][lk + j][lrow * 2] = make_float2(av, av);
        *(float2*)&As2[0][lk + 4 + j][lrow * 2] = make_float2(aw, aw);
        Bs[0][lk + j][lrow] = (&b0.x)[j];
        Bs[0][lk + 4 + j][lrow] = (&b1.x)[j];
    }
    __syncthreads();

    for (int kt = 0; kt < 32; kt++) {
        const int buf = kt & 1;
        if (kt < 31) {
            a0 = *(const float4*)(Arow + (kt + 1) * 16);
            a1 = *(const float4*)(Arow + (kt + 1) * 16 + 4);
            b0 = *(const float4*)(Brow + (kt + 1) * 16);
            b1 = *(const float4*)(Brow + (kt + 1) * 16 + 4);
        }
#pragma unroll
        for (int k = 0; k < 16; k++) {
            u64t ap[8], bp[4];
            // packed broadcast A: LDS.128 yields {a_i,a_i,a_{i+1},a_{i+1}} = 2 u64s
            *(uint4*)&ap[0] = *(const uint4*)&As2[buf][k][(ty * 8 + 0) * 2];
            *(uint4*)&ap[2] = *(const uint4*)&As2[buf][k][(ty * 8 + 2) * 2];
            *(uint4*)&ap[4] = *(const uint4*)&As2[buf][k][(ty * 8 + 4) * 2];
            *(uint4*)&ap[6] = *(const uint4*)&As2[buf][k][(ty * 8 + 6) * 2];
            // packed B pairs: LDS.128 = 2 u64 pairs
            *(uint4*)&bp[0] = *(const uint4*)&Bs[buf][k][tx * 8];
            *(uint4*)&bp[2] = *(const uint4*)&Bs[buf][k][tx * 8 + 4];
#pragma unroll
            for (int i = 0; i < 8; i++)
#pragma unroll
                for (int q = 0; q < 4; q++) FMA2(acc2[i][q], ap[i], bp[q], acc2[i][q]);
        }
        if (kt < 31) {
            const int nb = buf ^ 1;
#pragma unroll
            for (int j = 0; j < 4; j++) {
                float av = (&a0.x)[j], aw = (&a1.x)[j];
                *(float2*)&As2[nb][lk + j][lrow * 2] = make_float2(av, av);
                *(float2*)&As2[nb][lk + 4 + j][lrow * 2] = make_float2(aw, aw);
                Bs[nb][lk + j][lrow] = (&b0.x)[j];
                Bs[nb][lk + 4 + j][lrow] = (&b1.x)[j];
            }
            __syncthreads();
        }
    }
#pragma unroll
    for (int i = 0; i < 8; i++) {
        int n = mb + ty * 8 + i;
#pragma unroll
        for (int q = 0; q < 4; q++) {
            float lo, hi;
            UNPACKF2(lo, hi, acc2[i][q]);
            *(float2*)&C[(size_t)n * FD + jb + tx * 8 + q * 2] = make_float2(lo, hi);
        }
    }
}

// ---------------- attention: logits chain + XLA softmax (verbatim) ----------------
__global__ __launch_bounds__(256) void k_attn(int cur, const float* __restrict__ G) {
    __shared__ float Gs[Kk * 129];
    const float* __restrict__ h = g_h[cur];
    const int warp = threadIdx.x >> 5, lane = threadIdx.x & 31;
    const int n0 = blockIdx.x * 32 + warp * 4;
    float acc[4][2];
#pragma unroll
    for (int r = 0; r < 4; r++) { acc[r][0] = 0.f; acc[r][1] = 0.f; }

    for (int ch = 0; ch < 4; ch++) {
        __syncthreads();
        for (int e = threadIdx.x; e < Kk * 128; e += 256)
            Gs[(e >> 7) * 129 + (e & 127)] = G[(e >> 7) * Dd + ch * 128 + (e & 127)];
        __syncthreads();
#pragma unroll 2
        for (int d = 0; d < 128; d++) {
            float w0 = Gs[lane * 129 + d];
            float w1 = Gs[(lane + 32) * 129 + d];
#pragma unroll
            for (int r = 0; r < 4; r++) {
                float hv = h[(size_t)(n0 + r) * Dd + ch * 128 + d];
                acc[r][0] = fmaf(hv, w0, acc[r][0]);
                acc[r][1] = fmaf(hv, w1, acc[r][1]);
            }
        }
    }
#pragma unroll
    for (int r = 0; r < 4; r++) {
        float m = fmaxf(acc[r][0], acc[r][1]);
#pragma unroll
        for (int off = 16; off; off >>= 1) m = fmaxf(m, __shfl_xor_sync(0xffffffffu, m, off));
        float e0 = expf(acc[r][0] - m);
        float e1 = expf(acc[r][1] - m);
        float s = __fadd_rn(e0, e1);
#pragma unroll
        for (int off = 16; off; off >>= 1) s = __fadd_rn(s, __shfl_xor_sync(0xffffffffu, s, off));
        s = __shfl_sync(0xffffffffu, s, 0);
        g_a[(size_t)(n0 + r) * Kk + lane]      = __fdiv_rn(e0, s);
        g_a[(size_t)(n0 + r) * Kk + lane + 32] = __fdiv_rn(e1, s);
    }
}

// ---------------- r = a @ G : FFMA2, serial ascending k chain ----------------
__global__ __launch_bounds__(256) void k_r(const float* __restrict__ G) {
    __shared__ float Gs[Kk][128];
    __shared__ float as2[32][Kk * 2];     // duplicated a values: {v,v}
    const int d0 = blockIdx.x * 128, n0 = blockIdx.y * 32;
    const int tid = threadIdx.x;
    const int dthr = tid & 31, rgrp = tid >> 5;

    for (int e = tid; e < Kk * 128; e += 256)
        Gs[e >> 7][e & 127] = G[(size_t)(e >> 7) * Dd + d0 + (e & 127)];
    for (int e = tid; e < 32 * Kk; e += 256) {
        float v = g_a[(size_t)(n0 + (e >> 6)) * Kk + (e & 63)];
        *(float2*)&as2[e >> 6][(e & 63) * 2] = make_float2(v, v);
    }
    __syncthreads();

    u64t acc2[4][2];
#pragma unroll
    for (int r = 0; r < 4; r++) { acc2[r][0] = 0ull; acc2[r][1] = 0ull; }
    for (int k = 0; k < Kk; k++) {
        u64t g2[2];
        *(uint4*)&g2[0] = *(const uint4*)&Gs[k][dthr * 4];
#pragma unroll
        for (int r = 0; r < 4; r++) {
            u64t a2 = *(const u64t*)&as2[rgrp * 4 + r][k * 2];
            FMA2(acc2[r][0], a2, g2[0], acc2[r][0]);
            FMA2(acc2[r][1], a2, g2[1], acc2[r][1]);
        }
    }
#pragma unroll
    for (int r = 0; r < 4; r++) {
        float x0, x1, x2, x3;
        UNPACKF2(x0, x1, acc2[r][0]);
        UNPACKF2(x2, x3, acc2[r][1]);
        *(float4*)&g_r[(size_t)(n0 + rgrp * 4 + r) * Dd + d0 + dthr * 4] = make_float4(x0, x1, x2, x3);
    }
}

// ---------------- x-chain GEMM (resumed from g_P), zero-MOV FFMA2 + fused LSTM ----------------
__global__ __launch_bounds__(256, 2) void k_gx(int cur, const float* __restrict__ Wih,
        const float* __restrict__ bih, const float* __restrict__ bhh,
        const float* __restrict__ f, float* __restrict__ dout, int last) {
    __shared__ float As2[2][16][256];
    __shared__ float Bs[2][16][128];
    float* __restrict__ hout = last ? dout : g_h[cur ^ 1];
    const int dcb = blockIdx.x * 32, mb = blockIdx.y * 128;
    const int tid = threadIdx.x, tx = tid & 15, ty = tid >> 4;
    const int lrow = tid >> 1, lk = (tid & 1) << 3;
    const size_t bj = (size_t)((lrow >> 5) * Dd + dcb + (lrow & 31));

    const float* Arow = g_r + (size_t)(mb + lrow) * Dd + lk;
    const float* Brow = Wih + bj * 1024 + 512 + lk;

    u64t acc2[8][4];
#pragma unroll
    for (int i = 0; i < 8; i++) {
        int n = mb + ty * 8 + i;
#pragma unroll
        for (int g = 0; g < 4; g++) {
            float2 v = *(const float2*)&g_P[(size_t)n * FD + g * Dd + dcb + tx * 2];
            PACKF2(acc2[i][g], v.x, v.y);
        }
    }

    float4 a0 = *(const float4*)(Arow), a1 = *(const float4*)(Arow + 4);
    float4 b0 = *(const float4*)(Brow), b1 = *(const float4*)(Brow + 4);
#pragma unroll
    for (int j = 0; j < 4; j++) {
        float av = (&a0.x)[j], aw = (&a1.x)[j];
        *(float2*)&As2[0][lk + j][lrow * 2] = make_float2(av, av);
        *(float2*)&As2[0][lk + 4 + j][lrow * 2] = make_float2(aw, aw);
        Bs[0][lk + j][lrow] = (&b0.x)[j];
        Bs[0][lk + 4 + j][lrow] = (&b1.x)[j];
    }
    __syncthreads();

    for (int kt = 0; kt < 32; kt++) {
        const int buf = kt & 1;
        if (kt < 31) {
            a0 = *(const float4*)(Arow + (kt + 1) * 16);
            a1 = *(const float4*)(Arow + (kt + 1) * 16 + 4);
            b0 = *(const float4*)(Brow + (kt + 1) * 16);
            b1 = *(const float4*)(Brow + (kt + 1) * 16 + 4);
        }
#pragma unroll
        for (int k = 0; k < 16; k++) {
            u64t ap[8], bp[4];
            *(uint4*)&ap[0] = *(const uint4*)&As2[buf][k][(ty * 8 + 0) * 2];
            *(uint4*)&ap[2] = *(const uint4*)&As2[buf][k][(ty * 8 + 2) * 2];
            *(uint4*)&ap[4] = *(const uint4*)&As2[buf][k][(ty * 8 + 4) * 2];
            *(uint4*)&ap[6] = *(const uint4*)&As2[buf][k][(ty * 8 + 6) * 2];
#pragma unroll
            for (int g = 0; g < 4; g++)
                bp[g] = *(const u64t*)&Bs[buf][k][g * 32 + tx * 2];
#pragma unroll
            for (int i = 0; i < 8; i++)
#pragma unroll
                for (int g = 0; g < 4; g++) FMA2(acc2[i][g], ap[i], bp[g], acc2[i][g]);
        }
        if (kt < 31) {
            const int nb = buf ^ 1;
#pragma unroll
            for (int j = 0; j < 4; j++) {
                float av = (&a0.x)[j], aw = (&a1.x)[j];
                *(float2*)&As2[nb][lk + j][lrow * 2] = make_float2(av, av);
                *(float2*)&As2[nb][lk + 4 + j][lrow * 2] = make_float2(aw, aw);
                Bs[nb][lk + j][lrow] = (&b0.x)[j];
                Bs[nb][lk + 4 + j][lrow] = (&b1.x)[j];
            }
            __syncthreads();
        }
    }

    // epilogue: ((x + b_ih) + hW) + b_hh, XLA pointwise (identical), write c / h
#pragma unroll
    for (int i = 0; i < 8; i++) {
        int n = mb + ty * 8 + i;
        const float* hwp = &g_hw[(size_t)n * FD];
        float ax[8];
#pragma unroll
        for (int g = 0; g < 4; g++) UNPACKF2(ax[g * 2], ax[g * 2 + 1], acc2[i][g]);
#pragma unroll
        for (int p = 0; p < 2; p++) {
            int dc = dcb + tx * 2 + p;
            float iv = __fadd_rn(__fadd_rn(__fadd_rn(ax[0 + p], bih[0 * Dd + dc]), hwp[0 * Dd + dc]), bhh[0 * Dd + dc]);
            float fv = __fadd_rn(__fadd_rn(__fadd_rn(ax[2 + p], bih[1 * Dd + dc]), hwp[1 * Dd + dc]), bhh[1 * Dd + dc]);
            float gv = __fadd_rn(__fadd_rn(__fadd_rn(ax[4 + p], bih[2 * Dd + dc]), hwp[2 * Dd + dc]), bhh[2 * Dd + dc]);
            float ov = __fadd_rn(__fadd_rn(__fadd_rn(ax[6 + p], bih[3 * Dd + dc]), hwp[3 * Dd + dc]), bhh[3 * Dd + dc]);
            float co = g_c[(size_t)n * Dd + dc];
            float cn = __fadd_rn(__fmul_rn(sig_xla(fv), co), __fmul_rn(sig_xla(iv), tanh_xla(gv)));
            float hn = __fadd_rn(__fmul_rn(sig_xla(ov), tanh_xla(cn)), f[(size_t)n * Dd + dc]);
            g_c[(size_t)n * Dd + dc] = cn;
            hout[(size_t)n * Dd + dc] = hn;
        }
    }
}

extern "C" void kernel_launch(void* const* d_in, const int* in_sizes, int n_in,
                              void* d_out, int out_size) {
    const float* f   = (const float*)d_in[0];
    const float* G   = (const float*)d_in[1];
    const float* Wih = (const float*)d_in[2];
    const float* Whh = (const float*)d_in[3];
    const float* bih = (const float*)d_in[4];
    const float* bhh = (const float*)d_in[5];
    float* out = (float*)d_out;

    k_init<<<(Nn * Dd) / 256, 256>>>(f);
    {
        float* Pp; cudaGetSymbolAddress((void**)&Pp, g_P);
        k_gemm<<<dim3(FD / 128, Nn / 128), 256>>>(f, 0, Wih, 1024, Pp);
    }
    float* hwp; cudaGetSymbolAddress((void**)&hwp, g_hw);

    for (int s = 0; s < Kk; s++) {
        k_attn<<<Nn / 32, 256>>>(s & 1, G);
        k_r<<<dim3(Dd / 128, Nn / 32), 256>>>(G);
        k_gemm<<<dim3(FD / 128, Nn / 128), 256>>>((const float*)0, s & 1, Whh, 512, hwp);
        k_gx<<<dim3(Dd / 32, Nn / 128), 256>>>(s & 1, Wih, bih, bhh, f, out, s == Kk - 1);
    }
}

// round 9
// speedup vs baseline: 2.2033x; 2.2033x over previous
#include <cuda_runtime.h>
#include <math.h>

#define Nn 8192
#define Kk 64
#define Dd 512
#define FD 2048   // 4*D

typedef unsigned long long u64t;

// ---- packed f32x2 ops (Blackwell FFMA2; each half = independent IEEE rn FMA) ----
#define PACKF2(d, lo, hi)  asm("mov.b64 %0, {%1, %2};" : "=l"(d) : "f"(lo), "f"(hi))
#define UNPACKF2(lo, hi, s) asm("mov.b64 {%0, %1}, %2;" : "=f"(lo), "=f"(hi) : "l"(s))
#define FMA2(d, a, b, c)   asm("fma.rn.f32x2 %0, %1, %2, %3;" : "=l"(d) : "l"(a), "l"(b), "l"(c))

// Scratch (allocation-free device globals)
__device__ float g_P[(size_t)Nn * FD];      // 64 MB: partial chain f@W_L^T (no biases)
__device__ float g_hw[(size_t)Nn * FD];     // 64 MB: h@W_hh^T per step
__device__ float g_h[2][(size_t)Nn * Dd];   // ping/pong h
__device__ float g_c[(size_t)Nn * Dd];      // cell state
__device__ float g_r[(size_t)Nn * Dd];      // r = a @ G
__device__ float g_a[(size_t)Nn * Kk];      // softmax weights

// ---- XLA EmitFastTanh f32 (verbatim) ----
__device__ __forceinline__ float tanh_xla(float x) {
    float ax = fabsf(x);
    float xc = fminf(fmaxf(x, -7.90531110763549805f), 7.90531110763549805f);
    float x2 = __fmul_rn(xc, xc);
    float p = -2.76076847742355e-16f;
    p = __fadd_rn(__fmul_rn(p, x2), 2.00018790482477e-13f);
    p = __fadd_rn(__fmul_rn(p, x2), -8.60467152213735e-11f);
    p = __fadd_rn(__fmul_rn(p, x2), 5.12229709037114e-08f);
    p = __fadd_rn(__fmul_rn(p, x2), 1.48572235717979e-05f);
    p = __fadd_rn(__fmul_rn(p, x2), 6.37261928875436e-04f);
    p = __fadd_rn(__fmul_rn(p, x2), 4.89352455891786e-03f);
    float num = __fmul_rn(xc, p);
    float q = 1.19825839466702e-06f;
    q = __fadd_rn(__fmul_rn(q, x2), 1.18534705686654e-04f);
    q = __fadd_rn(__fmul_rn(q, x2), 2.26843463243900e-03f);
    q = __fadd_rn(__fmul_rn(q, x2), 4.89352518554385e-03f);
    float r = __fdiv_rn(num, q);
    return (ax < 0.0004f) ? x : r;
}
__device__ __forceinline__ float sig_xla(float x) {
    return __fadd_rn(0.5f, __fmul_rn(0.5f, tanh_xla(__fmul_rn(0.5f, x))));
}

// ---------------- init: h0 = f, c = 0 ----------------
__global__ void k_init(const float* __restrict__ f) {
    int i = blockIdx.x * 256 + threadIdx.x;
    g_h[0][i] = f[i];
    g_c[i] = 0.f;
}

// ---------------- generic SGEMM via FFMA2 ----------------
// 128x128 tile, 256 threads, 8x8/thread. Thread cols: {tx*4..+3, 64+tx*4..+3}
// (contiguous 16B per lane -> conflict-free LDS.128, B pairs load pre-packed).
__global__ __launch_bounds__(256, 2) void k_gemm(const float* __restrict__ Aopt, int cur,
                                                 const float* __restrict__ B, long bstride,
                                                 float* __restrict__ C) {
    __shared__ float As[2][16][128];
    __shared__ float Bs[2][16][128];
    const float* __restrict__ A = Aopt ? Aopt : g_h[cur];
    const int jb = blockIdx.x * 128, mb = blockIdx.y * 128;
    const int tid = threadIdx.x, tx = tid & 15, ty = tid >> 4;
    const int lrow = tid >> 1, lk = (tid & 1) << 3;
    u64t acc2[8][4];
#pragma unroll
    for (int i = 0; i < 8; i++)
#pragma unroll
        for (int q = 0; q < 4; q++) acc2[i][q] = 0ull;

    const float* Arow = A + (size_t)(mb + lrow) * Dd + lk;
    const float* Brow = B + (size_t)(jb + lrow) * bstride + lk;

    float4 a0 = *(const float4*)(Arow), a1 = *(const float4*)(Arow + 4);
    float4 b0 = *(const float4*)(Brow), b1 = *(const float4*)(Brow + 4);
    As[0][lk + 0][lrow] = a0.x; As[0][lk + 1][lrow] = a0.y; As[0][lk + 2][lrow] = a0.z; As[0][lk + 3][lrow] = a0.w;
    As[0][lk + 4][lrow] = a1.x; As[0][lk + 5][lrow] = a1.y; As[0][lk + 6][lrow] = a1.z; As[0][lk + 7][lrow] = a1.w;
    Bs[0][lk + 0][lrow] = b0.x; Bs[0][lk + 1][lrow] = b0.y; Bs[0][lk + 2][lrow] = b0.z; Bs[0][lk + 3][lrow] = b0.w;
    Bs[0][lk + 4][lrow] = b1.x; Bs[0][lk + 5][lrow] = b1.y; Bs[0][lk + 6][lrow] = b1.z; Bs[0][lk + 7][lrow] = b1.w;
    __syncthreads();

    for (int kt = 0; kt < 32; kt++) {
        const int buf = kt & 1;
        if (kt < 31) {
            a0 = *(const float4*)(Arow + (kt + 1) * 16);
            a1 = *(const float4*)(Arow + (kt + 1) * 16 + 4);
            b0 = *(const float4*)(Brow + (kt + 1) * 16);
            b1 = *(const float4*)(Brow + (kt + 1) * 16 + 4);
        }
#pragma unroll
        for (int k = 0; k < 16; k++) {
            float ar[8];
            *(float4*)&ar[0] = *(const float4*)&As[buf][k][ty * 8];
            *(float4*)&ar[4] = *(const float4*)&As[buf][k][ty * 8 + 4];
            u64t ap[8], bp[4];
#pragma unroll
            for (int i = 0; i < 8; i++) PACKF2(ap[i], ar[i], ar[i]);
            // B pairs pre-packed: contiguous 16B per lane, conflict-free
            *(uint4*)&bp[0] = *(const uint4*)&Bs[buf][k][tx * 4];
            *(uint4*)&bp[2] = *(const uint4*)&Bs[buf][k][64 + tx * 4];
#pragma unroll
            for (int i = 0; i < 8; i++)
#pragma unroll
                for (int q = 0; q < 4; q++) FMA2(acc2[i][q], ap[i], bp[q], acc2[i][q]);
        }
        if (kt < 31) {
            const int nb = buf ^ 1;
            As[nb][lk + 0][lrow] = a0.x; As[nb][lk + 1][lrow] = a0.y; As[nb][lk + 2][lrow] = a0.z; As[nb][lk + 3][lrow] = a0.w;
            As[nb][lk + 4][lrow] = a1.x; As[nb][lk + 5][lrow] = a1.y; As[nb][lk + 6][lrow] = a1.z; As[nb][lk + 7][lrow] = a1.w;
            Bs[nb][lk + 0][lrow] = b0.x; Bs[nb][lk + 1][lrow] = b0.y; Bs[nb][lk + 2][lrow] = b0.z; Bs[nb][lk + 3][lrow] = b0.w;
            Bs[nb][lk + 4][lrow] = b1.x; Bs[nb][lk + 5][lrow] = b1.y; Bs[nb][lk + 6][lrow] = b1.z; Bs[nb][lk + 7][lrow] = b1.w;
            __syncthreads();
        }
    }
#pragma unroll
    for (int i = 0; i < 8; i++) {
        int n = mb + ty * 8 + i;
#pragma unroll
        for (int q = 0; q < 2; q++) {
            float lo, hi;
            UNPACKF2(lo, hi, acc2[i][q]);
            *(float2*)&C[(size_t)n * FD + jb + tx * 4 + q * 2] = make_float2(lo, hi);
        }
#pragma unroll
        for (int q = 2; q < 4; q++) {
            float lo, hi;
            UNPACKF2(lo, hi, acc2[i][q]);
            *(float2*)&C[(size_t)n * FD + jb + 64 + tx * 4 + (q - 2) * 2] = make_float2(lo, hi);
        }
    }
}

// ---------------- attention: logits chain + XLA softmax (verbatim) ----------------
__global__ __launch_bounds__(256) void k_attn(int cur, const float* __restrict__ G) {
    __shared__ float Gs[Kk * 129];
    const float* __restrict__ h = g_h[cur];
    const int warp = threadIdx.x >> 5, lane = threadIdx.x & 31;
    const int n0 = blockIdx.x * 32 + warp * 4;
    float acc[4][2];
#pragma unroll
    for (int r = 0; r < 4; r++) { acc[r][0] = 0.f; acc[r][1] = 0.f; }

    for (int ch = 0; ch < 4; ch++) {
        __syncthreads();
        for (int e = threadIdx.x; e < Kk * 128; e += 256)
            Gs[(e >> 7) * 129 + (e & 127)] = G[(e >> 7) * Dd + ch * 128 + (e & 127)];
        __syncthreads();
#pragma unroll 2
        for (int d = 0; d < 128; d++) {
            float w0 = Gs[lane * 129 + d];
            float w1 = Gs[(lane + 32) * 129 + d];
#pragma unroll
            for (int r = 0; r < 4; r++) {
                float hv = h[(size_t)(n0 + r) * Dd + ch * 128 + d];
                acc[r][0] = fmaf(hv, w0, acc[r][0]);
                acc[r][1] = fmaf(hv, w1, acc[r][1]);
            }
        }
    }
#pragma unroll
    for (int r = 0; r < 4; r++) {
        float m = fmaxf(acc[r][0], acc[r][1]);
#pragma unroll
        for (int off = 16; off; off >>= 1) m = fmaxf(m, __shfl_xor_sync(0xffffffffu, m, off));
        float e0 = expf(acc[r][0] - m);
        float e1 = expf(acc[r][1] - m);
        float s = __fadd_rn(e0, e1);
#pragma unroll
        for (int off = 16; off; off >>= 1) s = __fadd_rn(s, __shfl_xor_sync(0xffffffffu, s, off));
        s = __shfl_sync(0xffffffffu, s, 0);
        g_a[(size_t)(n0 + r) * Kk + lane]      = __fdiv_rn(e0, s);
        g_a[(size_t)(n0 + r) * Kk + lane + 32] = __fdiv_rn(e1, s);
    }
}

// ---------------- r = a @ G : FFMA2, serial ascending k chain (R7 version) ----------------
__global__ __launch_bounds__(256) void k_r(const float* __restrict__ G) {
    __shared__ float Gs[Kk][128];
    __shared__ float as[32][Kk];
    const int d0 = blockIdx.x * 128, n0 = blockIdx.y * 32;
    const int tid = threadIdx.x;
    const int dthr = tid & 31, rgrp = tid >> 5;

    for (int e = tid; e < Kk * 128; e += 256)
        Gs[e >> 7][e & 127] = G[(size_t)(e >> 7) * Dd + d0 + (e & 127)];
    for (int e = tid; e < 32 * Kk; e += 256)
        as[e >> 6][e & 63] = g_a[(size_t)(n0 + (e >> 6)) * Kk + (e & 63)];
    __syncthreads();

    u64t acc2[4][2];
#pragma unroll
    for (int r = 0; r < 4; r++) { acc2[r][0] = 0ull; acc2[r][1] = 0ull; }
    for (int k = 0; k < Kk; k++) {
        u64t g2[2];
        *(uint4*)&g2[0] = *(const uint4*)&Gs[k][dthr * 4];
#pragma unroll
        for (int r = 0; r < 4; r++) {
            float av = as[rgrp * 4 + r][k];
            u64t a2;
            PACKF2(a2, av, av);
            FMA2(acc2[r][0], a2, g2[0], acc2[r][0]);
            FMA2(acc2[r][1], a2, g2[1], acc2[r][1]);
        }
    }
#pragma unroll
    for (int r = 0; r < 4; r++) {
        float x0, x1, x2, x3;
        UNPACKF2(x0, x1, acc2[r][0]);
        UNPACKF2(x2, x3, acc2[r][1]);
        *(float4*)&g_r[(size_t)(n0 + rgrp * 4 + r) * Dd + d0 + dthr * 4] = make_float4(x0, x1, x2, x3);
    }
}

// ---------------- x-chain GEMM (resumed from g_P) via FFMA2 + fused LSTM epilogue ----------------
// Thread cols: 4 gates x 2 dc (pair tx*2..+1) — B pairs load pre-packed via LDS.64.
__global__ __launch_bounds__(256, 2) void k_gx(int cur, const float* __restrict__ Wih,
        const float* __restrict__ bih, const float* __restrict__ bhh,
        const float* __restrict__ f, float* __restrict__ dout, int last) {
    __shared__ float As[2][16][128];
    __shared__ float Bs[2][16][128];
    float* __restrict__ hout = last ? dout : g_h[cur ^ 1];
    const int dcb = blockIdx.x * 32, mb = blockIdx.y * 128;
    const int tid = threadIdx.x, tx = tid & 15, ty = tid >> 4;
    const int lrow = tid >> 1, lk = (tid & 1) << 3;
    const size_t bj = (size_t)((lrow >> 5) * Dd + dcb + (lrow & 31));

    const float* Arow = g_r + (size_t)(mb + lrow) * Dd + lk;
    const float* Brow = Wih + bj * 1024 + 512 + lk;

    u64t acc2[8][4];
#pragma unroll
    for (int i = 0; i < 8; i++) {
        int n = mb + ty * 8 + i;
#pragma unroll
        for (int g = 0; g < 4; g++) {
            float2 v = *(const float2*)&g_P[(size_t)n * FD + g * Dd + dcb + tx * 2];
            PACKF2(acc2[i][g], v.x, v.y);
        }
    }

    float4 a0 = *(const float4*)(Arow), a1 = *(const float4*)(Arow + 4);
    float4 b0 = *(const float4*)(Brow), b1 = *(const float4*)(Brow + 4);
    As[0][lk + 0][lrow] = a0.x; As[0][lk + 1][lrow] = a0.y; As[0][lk + 2][lrow] = a0.z; As[0][lk + 3][lrow] = a0.w;
    As[0][lk + 4][lrow] = a1.x; As[0][lk + 5][lrow] = a1.y; As[0][lk + 6][lrow] = a1.z; As[0][lk + 7][lrow] = a1.w;
    Bs[0][lk + 0][lrow] = b0.x; Bs[0][lk + 1][lrow] = b0.y; Bs[0][lk + 2][lrow] = b0.z; Bs[0][lk + 3][lrow] = b0.w;
    Bs[0][lk + 4][lrow] = b1.x; Bs[0][lk + 5][lrow] = b1.y; Bs[0][lk + 6][lrow] = b1.z; Bs[0][lk + 7][lrow] = b1.w;
    __syncthreads();

    for (int kt = 0; kt < 32; kt++) {
        const int buf = kt & 1;
        if (kt < 31) {
            a0 = *(const float4*)(Arow + (kt + 1) * 16);
            a1 = *(const float4*)(Arow + (kt + 1) * 16 + 4);
            b0 = *(const float4*)(Brow + (kt + 1) * 16);
            b1 = *(const float4*)(Brow + (kt + 1) * 16 + 4);
        }
#pragma unroll
        for (int k = 0; k < 16; k++) {
            float ar[8];
            *(float4*)&ar[0] = *(const float4*)&As[buf][k][ty * 8];
            *(float4*)&ar[4] = *(const float4*)&As[buf][k][ty * 8 + 4];
            u64t ap[8], bp[4];
#pragma unroll
            for (int i = 0; i < 8; i++) PACKF2(ap[i], ar[i], ar[i]);
#pragma unroll
            for (int g = 0; g < 4; g++)
                bp[g] = *(const u64t*)&Bs[buf][k][g * 32 + tx * 2];   // pre-packed pair, conflict-free
#pragma unroll
            for (int i = 0; i < 8; i++)
#pragma unroll
                for (int g = 0; g < 4; g++) FMA2(acc2[i][g], ap[i], bp[g], acc2[i][g]);
        }
        if (kt < 31) {
            const int nb = buf ^ 1;
            As[nb][lk + 0][lrow] = a0.x; As[nb][lk + 1][lrow] = a0.y; As[nb][lk + 2][lrow] = a0.z; As[nb][lk + 3][lrow] = a0.w;
            As[nb][lk + 4][lrow] = a1.x; As[nb][lk + 5][lrow] = a1.y; As[nb][lk + 6][lrow] = a1.z; As[nb][lk + 7][lrow] = a1.w;
            Bs[nb][lk + 0][lrow] = b0.x; Bs[nb][lk + 1][lrow] = b0.y; Bs[nb][lk + 2][lrow] = b0.z; Bs[nb][lk + 3][lrow] = b0.w;
            Bs[nb][lk + 4][lrow] = b1.x; Bs[nb][lk + 5][lrow] = b1.y; Bs[nb][lk + 6][lrow] = b1.z; Bs[nb][lk + 7][lrow] = b1.w;
            __syncthreads();
        }
    }

    // epilogue: ((x + b_ih) + hW) + b_hh, XLA pointwise (identical), write c / h
#pragma unroll
    for (int i = 0; i < 8; i++) {
        int n = mb + ty * 8 + i;
        const float* hwp = &g_hw[(size_t)n * FD];
        float ax[8];
#pragma unroll
        for (int g = 0; g < 4; g++) UNPACKF2(ax[g * 2], ax[g * 2 + 1], acc2[i][g]);
#pragma unroll
        for (int p = 0; p < 2; p++) {
            int dc = dcb + tx * 2 + p;
            float iv = __fadd_rn(__fadd_rn(__fadd_rn(ax[0 + p], bih[0 * Dd + dc]), hwp[0 * Dd + dc]), bhh[0 * Dd + dc]);
            float fv = __fadd_rn(__fadd_rn(__fadd_rn(ax[2 + p], bih[1 * Dd + dc]), hwp[1 * Dd + dc]), bhh[1 * Dd + dc]);
            float gv = __fadd_rn(__fadd_rn(__fadd_rn(ax[4 + p], bih[2 * Dd + dc]), hwp[2 * Dd + dc]), bhh[2 * Dd + dc]);
            float ov = __fadd_rn(__fadd_rn(__fadd_rn(ax[6 + p], bih[3 * Dd + dc]), hwp[3 * Dd + dc]), bhh[3 * Dd + dc]);
            float co = g_c[(size_t)n * Dd + dc];
            float cn = __fadd_rn(__fmul_rn(sig_xla(fv), co), __fmul_rn(sig_xla(iv), tanh_xla(gv)));
            float hn = __fadd_rn(__fmul_rn(sig_xla(ov), tanh_xla(cn)), f[(size_t)n * Dd + dc]);
            g_c[(size_t)n * Dd + dc] = cn;
            hout[(size_t)n * Dd + dc] = hn;
        }
    }
}

extern "C" void kernel_launch(void* const* d_in, const int* in_sizes, int n_in,
                              void* d_out, int out_size) {
    const float* f   = (const float*)d_in[0];
    const float* G   = (const float*)d_in[1];
    const float* Wih = (const float*)d_in[2];
    const float* Whh = (const float*)d_in[3];
    const float* bih = (const float*)d_in[4];
    const float* bhh = (const float*)d_in[5];
    float* out = (float*)d_out;

    k_init<<<(Nn * Dd) / 256, 256>>>(f);
    {
        float* Pp; cudaGetSymbolAddress((void**)&Pp, g_P);
        k_gemm<<<dim3(FD / 128, Nn / 128), 256>>>(f, 0, Wih, 1024, Pp);
    }
    float* hwp; cudaGetSymbolAddress((void**)&hwp, g_hw);

    for (int s = 0; s < Kk; s++) {
        k_attn<<<Nn / 32, 256>>>(s & 1, G);
        k_r<<<dim3(Dd / 128, Nn / 32), 256>>>(G);
        k_gemm<<<dim3(FD / 128, Nn / 128), 256>>>((const float*)0, s & 1, Whh, 512, hwp);
        k_gx<<<dim3(Dd / 32, Nn / 128), 256>>>(s & 1, Wih, bih, bhh, f, out, s == Kk - 1);
    }
}

// round 10
// speedup vs baseline: 2.2766x; 1.0333x over previous
#include <cuda_runtime.h>
#include <math.h>

#define Nn 8192
#define Kk 64
#define Dd 512
#define FD 2048   // 4*D

typedef unsigned long long u64t;

// ---- packed f32x2 ops (Blackwell FFMA2; each half = independent IEEE rn FMA) ----
#define PACKF2(d, lo, hi)  asm("mov.b64 %0, {%1, %2};" : "=l"(d) : "f"(lo), "f"(hi))
#define UNPACKF2(lo, hi, s) asm("mov.b64 {%0, %1}, %2;" : "=f"(lo), "=f"(hi) : "l"(s))
#define FMA2(d, a, b, c)   asm("fma.rn.f32x2 %0, %1, %2, %3;" : "=l"(d) : "l"(a), "l"(b), "l"(c))

// Scratch (allocation-free device globals)
__device__ float g_P[(size_t)Nn * FD];      // 64 MB: partial chain f@W_L^T (no biases)
__device__ float g_hw[(size_t)Nn * FD];     // 64 MB: h@W_hh^T per step
__device__ float g_h[2][(size_t)Nn * Dd];   // ping/pong h
__device__ float g_c[(size_t)Nn * Dd];      // cell state
__device__ float g_r[(size_t)Nn * Dd];      // r = a @ G

// ---- XLA EmitFastTanh f32 (verbatim) ----
__device__ __forceinline__ float tanh_xla(float x) {
    float ax = fabsf(x);
    float xc = fminf(fmaxf(x, -7.90531110763549805f), 7.90531110763549805f);
    float x2 = __fmul_rn(xc, xc);
    float p = -2.76076847742355e-16f;
    p = __fadd_rn(__fmul_rn(p, x2), 2.00018790482477e-13f);
    p = __fadd_rn(__fmul_rn(p, x2), -8.60467152213735e-11f);
    p = __fadd_rn(__fmul_rn(p, x2), 5.12229709037114e-08f);
    p = __fadd_rn(__fmul_rn(p, x2), 1.48572235717979e-05f);
    p = __fadd_rn(__fmul_rn(p, x2), 6.37261928875436e-04f);
    p = __fadd_rn(__fmul_rn(p, x2), 4.89352455891786e-03f);
    float num = __fmul_rn(xc, p);
    float q = 1.19825839466702e-06f;
    q = __fadd_rn(__fmul_rn(q, x2), 1.18534705686654e-04f);
    q = __fadd_rn(__fmul_rn(q, x2), 2.26843463243900e-03f);
    q = __fadd_rn(__fmul_rn(q, x2), 4.89352518554385e-03f);
    float r = __fdiv_rn(num, q);
    return (ax < 0.0004f) ? x : r;
}
__device__ __forceinline__ float sig_xla(float x) {
    return __fadd_rn(0.5f, __fmul_rn(0.5f, tanh_xla(__fmul_rn(0.5f, x))));
}

// ---------------- init: h0 = f, c = 0 ----------------
__global__ void k_init(const float* __restrict__ f) {
    int i = blockIdx.x * 256 + threadIdx.x;
    g_h[0][i] = f[i];
    g_c[i] = 0.f;
}

// Shared-memory overlay: gemm path 32768 B; attnr path 64*129*4 + 32*64*4 = 41216 B
#define SU_BYTES 41216

// ---- fused attention + r body: one CTA = 32 rows (rb in 0..255) ----
// Phase A == k_attn (verbatim chains), a kept in smem; Phase B == k_r chains per d-chunk.
__device__ __forceinline__ void attnr_body(char* su, int rb, const float* __restrict__ h,
                                           const float* __restrict__ G) {
    float* Gs = reinterpret_cast<float*>(su);                          // [64*129]
    float (*a2)[Kk] = reinterpret_cast<float(*)[Kk]>(su + Kk * 129 * 4);  // [32][64]
    const int tid = threadIdx.x;
    const int warp = tid >> 5, lane = tid & 31;
    const int n0 = rb * 32 + warp * 4;

    // ---- Phase A: logits + XLA softmax (identical arithmetic to k_attn) ----
    float acc[4][2];
#pragma unroll
    for (int r = 0; r < 4; r++) { acc[r][0] = 0.f; acc[r][1] = 0.f; }
    for (int ch = 0; ch < 4; ch++) {
        __syncthreads();
        for (int e = tid; e < Kk * 128; e += 256)
            Gs[(e >> 7) * 129 + (e & 127)] = G[(e >> 7) * Dd + ch * 128 + (e & 127)];
        __syncthreads();
#pragma unroll 2
        for (int d = 0; d < 128; d++) {
            float w0 = Gs[lane * 129 + d];
            float w1 = Gs[(lane + 32) * 129 + d];
#pragma unroll
            for (int r = 0; r < 4; r++) {
                float hv = h[(size_t)(n0 + r) * Dd + ch * 128 + d];
                acc[r][0] = fmaf(hv, w0, acc[r][0]);
                acc[r][1] = fmaf(hv, w1, acc[r][1]);
            }
        }
    }
#pragma unroll
    for (int r = 0; r < 4; r++) {
        float m = fmaxf(acc[r][0], acc[r][1]);
#pragma unroll
        for (int off = 16; off; off >>= 1) m = fmaxf(m, __shfl_xor_sync(0xffffffffu, m, off));
        float e0 = expf(acc[r][0] - m);
        float e1 = expf(acc[r][1] - m);
        float s = __fadd_rn(e0, e1);
#pragma unroll
        for (int off = 16; off; off >>= 1) s = __fadd_rn(s, __shfl_xor_sync(0xffffffffu, s, off));
        s = __shfl_sync(0xffffffffu, s, 0);
        a2[warp * 4 + r][lane]      = __fdiv_rn(e0, s);
        a2[warp * 4 + r][lane + 32] = __fdiv_rn(e1, s);
    }
    __syncthreads();   // a2 complete; Gs free for reuse

    // ---- Phase B: r = a @ G (identical chains to k_r), per 128-d chunk ----
    float (*Gr)[128] = reinterpret_cast<float(*)[128]>(su);
    const int dthr = tid & 31, rgrp = tid >> 5;
    for (int ch = 0; ch < 4; ch++) {
        for (int e = tid; e < Kk * 128; e += 256)
            Gr[e >> 7][e & 127] = G[(size_t)(e >> 7) * Dd + ch * 128 + (e & 127)];
        __syncthreads();
        u64t acc2[4][2];
#pragma unroll
        for (int r = 0; r < 4; r++) { acc2[r][0] = 0ull; acc2[r][1] = 0ull; }
        for (int k = 0; k < Kk; k++) {
            u64t g2[2];
            *(uint4*)&g2[0] = *(const uint4*)&Gr[k][dthr * 4];
#pragma unroll
            for (int r = 0; r < 4; r++) {
                float av = a2[rgrp * 4 + r][k];
                u64t av2;
                PACKF2(av2, av, av);
                FMA2(acc2[r][0], av2, g2[0], acc2[r][0]);
                FMA2(acc2[r][1], av2, g2[1], acc2[r][1]);
            }
        }
#pragma unroll
        for (int r = 0; r < 4; r++) {
            float x0, x1, x2, x3;
            UNPACKF2(x0, x1, acc2[r][0]);
            UNPACKF2(x2, x3, acc2[r][1]);
            *(float4*)&g_r[(size_t)(rb * 32 + rgrp * 4 + r) * Dd + ch * 128 + dthr * 4] =
                make_float4(x0, x1, x2, x3);
        }
        __syncthreads();   // Gr reads done before next chunk overwrite
    }
}

// ---------------- merged launch: gemm tiles + attnr CTAs ----------------
// If G != null: grid (20, 64); x<4 -> attnr (rb = y*4+x), x>=4 -> gemm tile jb=(x-4)*128.
// If G == null: pure gemm, grid (16, 64), jb = x*128 (used for P precompute).
__global__ __launch_bounds__(256, 2) void k_gemm(const float* __restrict__ Aopt, int cur,
                                                 const float* __restrict__ B, long bstride,
                                                 float* __restrict__ C,
                                                 const float* __restrict__ G) {
    __shared__ __align__(16) char su[SU_BYTES];
    const float* __restrict__ A = Aopt ? Aopt : g_h[cur];
    int jb;
    if (G) {
        if (blockIdx.x < 4) { attnr_body(su, blockIdx.y * 4 + blockIdx.x, A, G); return; }
        jb = (blockIdx.x - 4) * 128;
    } else {
        jb = blockIdx.x * 128;
    }
    float (*As)[16][128] = reinterpret_cast<float(*)[16][128]>(su);
    float (*Bs)[16][128] = reinterpret_cast<float(*)[16][128]>(su + 16384);
    const int mb = blockIdx.y * 128;
    const int tid = threadIdx.x, tx = tid & 15, ty = tid >> 4;
    const int lrow = tid >> 1, lk = (tid & 1) << 3;
    u64t acc2[8][4];
#pragma unroll
    for (int i = 0; i < 8; i++)
#pragma unroll
        for (int q = 0; q < 4; q++) acc2[i][q] = 0ull;

    const float* Arow = A + (size_t)(mb + lrow) * Dd + lk;
    const float* Brow = B + (size_t)(jb + lrow) * bstride + lk;

    float4 a0 = *(const float4*)(Arow), a1 = *(const float4*)(Arow + 4);
    float4 b0 = *(const float4*)(Brow), b1 = *(const float4*)(Brow + 4);
    As[0][lk + 0][lrow] = a0.x; As[0][lk + 1][lrow] = a0.y; As[0][lk + 2][lrow] = a0.z; As[0][lk + 3][lrow] = a0.w;
    As[0][lk + 4][lrow] = a1.x; As[0][lk + 5][lrow] = a1.y; As[0][lk + 6][lrow] = a1.z; As[0][lk + 7][lrow] = a1.w;
    Bs[0][lk + 0][lrow] = b0.x; Bs[0][lk + 1][lrow] = b0.y; Bs[0][lk + 2][lrow] = b0.z; Bs[0][lk + 3][lrow] = b0.w;
    Bs[0][lk + 4][lrow] = b1.x; Bs[0][lk + 5][lrow] = b1.y; Bs[0][lk + 6][lrow] = b1.z; Bs[0][lk + 7][lrow] = b1.w;
    __syncthreads();

    for (int kt = 0; kt < 32; kt++) {
        const int buf = kt & 1;
        if (kt < 31) {
            a0 = *(const float4*)(Arow + (kt + 1) * 16);
            a1 = *(const float4*)(Arow + (kt + 1) * 16 + 4);
            b0 = *(const float4*)(Brow + (kt + 1) * 16);
            b1 = *(const float4*)(Brow + (kt + 1) * 16 + 4);
        }
#pragma unroll
        for (int k = 0; k < 16; k++) {
            float ar[8];
            *(float4*)&ar[0] = *(const float4*)&As[buf][k][ty * 8];
            *(float4*)&ar[4] = *(const float4*)&As[buf][k][ty * 8 + 4];
            u64t ap[8], bp[4];
#pragma unroll
            for (int i = 0; i < 8; i++) PACKF2(ap[i], ar[i], ar[i]);
            *(uint4*)&bp[0] = *(const uint4*)&Bs[buf][k][tx * 4];
            *(uint4*)&bp[2] = *(const uint4*)&Bs[buf][k][64 + tx * 4];
#pragma unroll
            for (int i = 0; i < 8; i++)
#pragma unroll
                for (int q = 0; q < 4; q++) FMA2(acc2[i][q], ap[i], bp[q], acc2[i][q]);
        }
        if (kt < 31) {
            const int nb = buf ^ 1;
            As[nb][lk + 0][lrow] = a0.x; As[nb][lk + 1][lrow] = a0.y; As[nb][lk + 2][lrow] = a0.z; As[nb][lk + 3][lrow] = a0.w;
            As[nb][lk + 4][lrow] = a1.x; As[nb][lk + 5][lrow] = a1.y; As[nb][lk + 6][lrow] = a1.z; As[nb][lk + 7][lrow] = a1.w;
            Bs[nb][lk + 0][lrow] = b0.x; Bs[nb][lk + 1][lrow] = b0.y; Bs[nb][lk + 2][lrow] = b0.z; Bs[nb][lk + 3][lrow] = b0.w;
            Bs[nb][lk + 4][lrow] = b1.x; Bs[nb][lk + 5][lrow] = b1.y; Bs[nb][lk + 6][lrow] = b1.z; Bs[nb][lk + 7][lrow] = b1.w;
            __syncthreads();
        }
    }
#pragma unroll
    for (int i = 0; i < 8; i++) {
        int n = mb + ty * 8 + i;
#pragma unroll
        for (int q = 0; q < 2; q++) {
            float lo, hi;
            UNPACKF2(lo, hi, acc2[i][q]);
            *(float2*)&C[(size_t)n * FD + jb + tx * 4 + q * 2] = make_float2(lo, hi);
        }
#pragma unroll
        for (int q = 2; q < 4; q++) {
            float lo, hi;
            UNPACKF2(lo, hi, acc2[i][q]);
            *(float2*)&C[(size_t)n * FD + jb + 64 + tx * 4 + (q - 2) * 2] = make_float2(lo, hi);
        }
    }
}

// ---------------- x-chain GEMM (resumed from g_P) via FFMA2 + fused LSTM epilogue ----------------
__global__ __launch_bounds__(256, 2) void k_gx(int cur, const float* __restrict__ Wih,
        const float* __restrict__ bih, const float* __restrict__ bhh,
        const float* __restrict__ f, float* __restrict__ dout, int last) {
    __shared__ float As[2][16][128];
    __shared__ float Bs[2][16][128];
    float* __restrict__ hout = last ? dout : g_h[cur ^ 1];
    const int dcb = blockIdx.x * 32, mb = blockIdx.y * 128;
    const int tid = threadIdx.x, tx = tid & 15, ty = tid >> 4;
    const int lrow = tid >> 1, lk = (tid & 1) << 3;
    const size_t bj = (size_t)((lrow >> 5) * Dd + dcb + (lrow & 31));

    const float* Arow = g_r + (size_t)(mb + lrow) * Dd + lk;
    const float* Brow = Wih + bj * 1024 + 512 + lk;

    u64t acc2[8][4];
#pragma unroll
    for (int i = 0; i < 8; i++) {
        int n = mb + ty * 8 + i;
#pragma unroll
        for (int g = 0; g < 4; g++) {
            float2 v = *(const float2*)&g_P[(size_t)n * FD + g * Dd + dcb + tx * 2];
            PACKF2(acc2[i][g], v.x, v.y);
        }
    }

    float4 a0 = *(const float4*)(Arow), a1 = *(const float4*)(Arow + 4);
    float4 b0 = *(const float4*)(Brow), b1 = *(const float4*)(Brow + 4);
    As[0][lk + 0][lrow] = a0.x; As[0][lk + 1][lrow] = a0.y; As[0][lk + 2][lrow] = a0.z; As[0][lk + 3][lrow] = a0.w;
    As[0][lk + 4][lrow] = a1.x; As[0][lk + 5][lrow] = a1.y; As[0][lk + 6][lrow] = a1.z; As[0][lk + 7][lrow] = a1.w;
    Bs[0][lk + 0][lrow] = b0.x; Bs[0][lk + 1][lrow] = b0.y; Bs[0][lk + 2][lrow] = b0.z; Bs[0][lk + 3][lrow] = b0.w;
    Bs[0][lk + 4][lrow] = b1.x; Bs[0][lk + 5][lrow] = b1.y; Bs[0][lk + 6][lrow] = b1.z; Bs[0][lk + 7][lrow] = b1.w;
    __syncthreads();

    for (int kt = 0; kt < 32; kt++) {
        const int buf = kt & 1;
        if (kt < 31) {
            a0 = *(const float4*)(Arow + (kt + 1) * 16);
            a1 = *(const float4*)(Arow + (kt + 1) * 16 + 4);
            b0 = *(const float4*)(Brow + (kt + 1) * 16);
            b1 = *(const float4*)(Brow + (kt + 1) * 16 + 4);
        }
#pragma unroll
        for (int k = 0; k < 16; k++) {
            float ar[8];
            *(float4*)&ar[0] = *(const float4*)&As[buf][k][ty * 8];
            *(float4*)&ar[4] = *(const float4*)&As[buf][k][ty * 8 + 4];
            u64t ap[8], bp[4];
#pragma unroll
            for (int i = 0; i < 8; i++) PACKF2(ap[i], ar[i], ar[i]);
#pragma unroll
            for (int g = 0; g < 4; g++)
                bp[g] = *(const u64t*)&Bs[buf][k][g * 32 + tx * 2];
#pragma unroll
            for (int i = 0; i < 8; i++)
#pragma unroll
                for (int g = 0; g < 4; g++) FMA2(acc2[i][g], ap[i], bp[g], acc2[i][g]);
        }
        if (kt < 31) {
            const int nb = buf ^ 1;
            As[nb][lk + 0][lrow] = a0.x; As[nb][lk + 1][lrow] = a0.y; As[nb][lk + 2][lrow] = a0.z; As[nb][lk + 3][lrow] = a0.w;
            As[nb][lk + 4][lrow] = a1.x; As[nb][lk + 5][lrow] = a1.y; As[nb][lk + 6][lrow] = a1.z; As[nb][lk + 7][lrow] = a1.w;
            Bs[nb][lk + 0][lrow] = b0.x; Bs[nb][lk + 1][lrow] = b0.y; Bs[nb][lk + 2][lrow] = b0.z; Bs[nb][lk + 3][lrow] = b0.w;
            Bs[nb][lk + 4][lrow] = b1.x; Bs[nb][lk + 5][lrow] = b1.y; Bs[nb][lk + 6][lrow] = b1.z; Bs[nb][lk + 7][lrow] = b1.w;
            __syncthreads();
        }
    }

    // epilogue: ((x + b_ih) + hW) + b_hh, XLA pointwise (identical), write c / h
#pragma unroll
    for (int i = 0; i < 8; i++) {
        int n = mb + ty * 8 + i;
        const float* hwp = &g_hw[(size_t)n * FD];
        float ax[8];
#pragma unroll
        for (int g = 0; g < 4; g++) UNPACKF2(ax[g * 2], ax[g * 2 + 1], acc2[i][g]);
#pragma unroll
        for (int p = 0; p < 2; p++) {
            int dc = dcb + tx * 2 + p;
            float iv = __fadd_rn(__fadd_rn(__fadd_rn(ax[0 + p], bih[0 * Dd + dc]), hwp[0 * Dd + dc]), bhh[0 * Dd + dc]);
            float fv = __fadd_rn(__fadd_rn(__fadd_rn(ax[2 + p], bih[1 * Dd + dc]), hwp[1 * Dd + dc]), bhh[1 * Dd + dc]);
            float gv = __fadd_rn(__fadd_rn(__fadd_rn(ax[4 + p], bih[2 * Dd + dc]), hwp[2 * Dd + dc]), bhh[2 * Dd + dc]);
            float ov = __fadd_rn(__fadd_rn(__fadd_rn(ax[6 + p], bih[3 * Dd + dc]), hwp[3 * Dd + dc]), bhh[3 * Dd + dc]);
            float co = g_c[(size_t)n * Dd + dc];
            float cn = __fadd_rn(__fmul_rn(sig_xla(fv), co), __fmul_rn(sig_xla(iv), tanh_xla(gv)));
            float hn = __fadd_rn(__fmul_rn(sig_xla(ov), tanh_xla(cn)), f[(size_t)n * Dd + dc]);
            g_c[(size_t)n * Dd + dc] = cn;
            hout[(size_t)n * Dd + dc] = hn;
        }
    }
}

extern "C" void kernel_launch(void* const* d_in, const int* in_sizes, int n_in,
                              void* d_out, int out_size) {
    const float* f   = (const float*)d_in[0];
    const float* G   = (const float*)d_in[1];
    const float* Wih = (const float*)d_in[2];
    const float* Whh = (const float*)d_in[3];
    const float* bih = (const float*)d_in[4];
    const float* bhh = (const float*)d_in[5];
    float* out = (float*)d_out;

    k_init<<<(Nn * Dd) / 256, 256>>>(f);
    {
        float* Pp; cudaGetSymbolAddress((void**)&Pp, g_P);
        k_gemm<<<dim3(FD / 128, Nn / 128), 256>>>(f, 0, Wih, 1024, Pp, (const float*)0);
    }
    float* hwp; cudaGetSymbolAddress((void**)&hwp, g_hw);

    for (int s = 0; s < Kk; s++) {
        // merged: x<4 -> fused attn+r CTAs (rb = y*4+x), x>=4 -> h@W_hh^T tiles
        k_gemm<<<dim3(FD / 128 + 4, Nn / 128), 256>>>((const float*)0, s & 1, Whh, 512, hwp, G);
        k_gx<<<dim3(Dd / 32, Nn / 128), 256>>>(s & 1, Wih, bih, bhh, f, out, s == Kk - 1);
    }
}